// round 2
// baseline (speedup 1.0000x reference)
#include <cuda_runtime.h>
#include <mma.h>
#include <cstdint>

using namespace nvcuda;

#define NN 8192
#define DD 256
#define NE 131072

#define BM 128
#define BN 64
#define BK 32
#define LDAS 36
#define LDBS 68
#define LDCS 68

// scratch (device globals; no allocations allowed)
__device__ float g_buf0[NN * DD];
__device__ float g_buf1[NN * DD];
__device__ float g_h[NN * DD];
__device__ float g_gout[NN * DD];
__device__ float g_deg[NN];

// C = A[M,K] @ B[K,BNcols]; if FUSE: Y = (resid + C) * 1/(rowsum(A)+1)
// A row-major lda, B row-major ldb, Y row-major DD wide.
template <bool FUSE>
__global__ __launch_bounds__(256) void gemm_kernel(
    const float* __restrict__ A, int lda,
    const float* __restrict__ B, int ldb,
    int K,
    const float* __restrict__ resid,
    float* __restrict__ Y)
{
    __shared__ float pool[BM * LDCS];   // reused: As+Bs during K loop, Cs in epilogue
    __shared__ float invs[BM];
    float* As = pool;                    // BM x LDAS
    float* Bs = pool + BM * LDAS;        // BK x LDBS

    const int tid = threadIdx.x;
    const int wid = tid >> 5;
    const int wm = wid & 3;              // warp row (0..3), 32 rows each
    const int wn = wid >> 2;             // warp col (0..1), 32 cols each
    const int m0 = blockIdx.y * BM;
    const int n0 = blockIdx.x * BN;

    wmma::fragment<wmma::accumulator, 16, 16, 8, float> cf[2][2];
#pragma unroll
    for (int i = 0; i < 2; i++)
#pragma unroll
        for (int j = 0; j < 2; j++) wmma::fill_fragment(cf[i][j], 0.0f);

    float rs[4] = {0.f, 0.f, 0.f, 0.f};
    const int arow = tid >> 3;           // 0..31
    const int ac4 = (tid & 7) * 4;       // 0..28

    for (int k0 = 0; k0 < K; k0 += BK) {
        // A tile: 128x32 floats, each thread 4 float4 from 4 fixed rows
#pragma unroll
        for (int j = 0; j < 4; j++) {
            int r = arow + 32 * j;
            float4 v = *(const float4*)&A[(size_t)(m0 + r) * lda + k0 + ac4];
            *(float4*)&As[r * LDAS + ac4] = v;
            if (FUSE) rs[j] += v.x + v.y + v.z + v.w;
        }
        // B tile: 32x64 floats, each thread 2 float4
        {
            int br = tid >> 4;
            int bc4 = (tid & 15) * 4;
            *(float4*)&Bs[br * LDBS + bc4] =
                *(const float4*)&B[(size_t)(k0 + br) * ldb + n0 + bc4];
            br += 16;
            *(float4*)&Bs[br * LDBS + bc4] =
                *(const float4*)&B[(size_t)(k0 + br) * ldb + n0 + bc4];
        }
        __syncthreads();
#pragma unroll
        for (int kk = 0; kk < BK; kk += 8) {
            wmma::fragment<wmma::matrix_a, 16, 16, 8, wmma::precision::tf32, wmma::row_major> af[2];
            wmma::fragment<wmma::matrix_b, 16, 16, 8, wmma::precision::tf32, wmma::row_major> bf[2];
#pragma unroll
            for (int i = 0; i < 2; i++) {
                wmma::load_matrix_sync(af[i], &As[(wm * 32 + i * 16) * LDAS + kk], LDAS);
#pragma unroll
                for (int t = 0; t < af[i].num_elements; t++)
                    af[i].x[t] = wmma::__float_to_tf32(af[i].x[t]);
            }
#pragma unroll
            for (int j = 0; j < 2; j++) {
                wmma::load_matrix_sync(bf[j], &Bs[kk * LDBS + wn * 32 + j * 16], LDBS);
#pragma unroll
                for (int t = 0; t < bf[j].num_elements; t++)
                    bf[j].x[t] = wmma::__float_to_tf32(bf[j].x[t]);
            }
#pragma unroll
            for (int i = 0; i < 2; i++)
#pragma unroll
                for (int j = 0; j < 2; j++)
                    wmma::mma_sync(cf[i][j], af[i], bf[j], cf[i][j]);
        }
        __syncthreads();
    }

    if (FUSE) {
        // rowsum: reduce across the 8 consecutive lanes sharing a row
#pragma unroll
        for (int j = 0; j < 4; j++) {
            float v = rs[j];
            v += __shfl_down_sync(0xffffffffu, v, 4, 8);
            v += __shfl_down_sync(0xffffffffu, v, 2, 8);
            v += __shfl_down_sync(0xffffffffu, v, 1, 8);
            if ((tid & 7) == 0) invs[arow + 32 * j] = 1.0f / (v + 1.0f);
        }
    }
    // stage C into shared (pool reused; all mma done due to loop-final syncthreads)
#pragma unroll
    for (int i = 0; i < 2; i++)
#pragma unroll
        for (int j = 0; j < 2; j++)
            wmma::store_matrix_sync(&pool[(wm * 32 + i * 16) * LDCS + wn * 32 + j * 16],
                                    cf[i][j], LDCS, wmma::mem_row_major);
    __syncthreads();
    // write 128x64 tile
#pragma unroll
    for (int it = 0; it < 8; it++) {
        int idx = tid + it * 256;            // 0..2047
        int r = idx >> 4;
        int c4 = (idx & 15) * 4;
        float4 c = *(float4*)&pool[r * LDCS + c4];
        if (FUSE) {
            float4 x = *(const float4*)&resid[(size_t)(m0 + r) * DD + n0 + c4];
            float s = invs[r];
            c.x = (c.x + x.x) * s;
            c.y = (c.y + x.y) * s;
            c.z = (c.z + x.z) * s;
            c.w = (c.w + x.w) * s;
        }
        *(float4*)&Y[(size_t)(m0 + r) * DD + n0 + c4] = c;
    }
}

__global__ void deg_reset(float* deg)
{
    int i = blockIdx.x * blockDim.x + threadIdx.x;
    if (i < NN) deg[i] = 1.0f;   // self loop
}

__global__ void deg_count(const int* __restrict__ dst, float* deg)
{
    int e = blockIdx.x * blockDim.x + threadIdx.x;
    if (e < NE) atomicAdd(&deg[dst[e]], 1.0f);
}

// out[n,:] = b + (1/deg[n]) * h[n,:]   (self-loop term, norm = dinv^2)
__global__ void gcn_init(const float* __restrict__ h, const float* __restrict__ deg,
                         const float* __restrict__ b, float* __restrict__ out)
{
    int idx = blockIdx.x * blockDim.x + threadIdx.x;   // NN*64 float4 items
    if (idx >= NN * (DD / 4)) return;
    int n = idx >> 6;
    int c4 = (idx & 63) * 4;
    float inv = 1.0f / deg[n];
    float4 hv = *(const float4*)&h[(size_t)n * DD + c4];
    float4 bv = *(const float4*)&b[c4];
    float4 o;
    o.x = bv.x + inv * hv.x;
    o.y = bv.y + inv * hv.y;
    o.z = bv.z + inv * hv.z;
    o.w = bv.w + inv * hv.w;
    *(float4*)&out[(size_t)n * DD + c4] = o;
}

__global__ void gcn_scatter(const int* __restrict__ src, const int* __restrict__ dst,
                            const float* __restrict__ h, const float* __restrict__ deg,
                            float* out)
{
    int idx = blockIdx.x * blockDim.x + threadIdx.x;   // NE*64 float4 items
    if (idx >= NE * (DD / 4)) return;
    int e = idx >> 6;
    int c4 = (idx & 63) * 4;
    int s = src[e];
    int d = dst[e];
    float norm = rsqrtf(deg[s]) * rsqrtf(deg[d]);
    float4 hv = *(const float4*)&h[(size_t)s * DD + c4];
    float* o = &out[(size_t)d * DD + c4];
    atomicAdd(o + 0, norm * hv.x);
    atomicAdd(o + 1, norm * hv.y);
    atomicAdd(o + 2, norm * hv.z);
    atomicAdd(o + 3, norm * hv.w);
}

extern "C" void kernel_launch(void* const* d_in, const int* in_sizes, int n_in,
                              void* d_out, int out_size)
{
    const float* emb    = (const float*)d_in[0];
    const float* paths  = (const float*)d_in[1];
    const int*   sm_ei  = (const int*)d_in[2];
    const int*   up_ei  = (const int*)d_in[3];
    const float* W_same = (const float*)d_in[4];
    const float* b_same = (const float*)d_in[5];
    const float* W_top  = (const float*)d_in[6];
    const float* b_top  = (const float*)d_in[7];
    float* out = (float*)d_out;

    float *buf0, *buf1, *h, *gout, *deg;
    cudaGetSymbolAddress((void**)&buf0, g_buf0);
    cudaGetSymbolAddress((void**)&buf1, g_buf1);
    cudaGetSymbolAddress((void**)&h, g_h);
    cudaGetSymbolAddress((void**)&gout, g_gout);
    cudaGetSymbolAddress((void**)&deg, g_deg);

    dim3 ggrid(DD / BN, NN / BM);   // (4, 64)
    dim3 gblk(256);

    // ---- bottom_to_up: level 0 and level 1
    gemm_kernel<true><<<ggrid, gblk>>>(paths, NN, emb, DD, NN, emb, buf0);
    gemm_kernel<true><<<ggrid, gblk>>>(paths + (size_t)NN * NN, NN, buf0, DD, NN, buf0, buf1);

    // ---- GCN 1 (same-level)
    gemm_kernel<false><<<ggrid, gblk>>>(buf1, DD, W_same, DD, DD, nullptr, h);
    deg_reset<<<(NN + 255) / 256, 256>>>(deg);
    deg_count<<<(NE + 255) / 256, 256>>>(sm_ei + NE, deg);
    gcn_init<<<(NN * (DD / 4) + 255) / 256, 256>>>(h, deg, b_same, gout);
    gcn_scatter<<<(NE * (DD / 4) + 255) / 256, 256>>>(sm_ei, sm_ei + NE, h, deg, gout);

    // ---- GCN 2 (top-to-bottom)
    gemm_kernel<false><<<ggrid, gblk>>>(gout, DD, W_top, DD, DD, nullptr, h);
    deg_reset<<<(NN + 255) / 256, 256>>>(deg);
    deg_count<<<(NE + 255) / 256, 256>>>(up_ei + NE, deg);
    gcn_init<<<(NN * (DD / 4) + 255) / 256, 256>>>(h, deg, b_top, out);
    gcn_scatter<<<(NE * (DD / 4) + 255) / 256, 256>>>(up_ei, up_ei + NE, h, deg, out);
}

// round 3
// speedup vs baseline: 1.1167x; 1.1167x over previous
#include <cuda_runtime.h>
#include <mma.h>
#include <cstdint>

using namespace nvcuda;

#define NN 8192
#define DD 256
#define NE 131072

#define BM 64
#define BN 256
#define BK 32
#define LDAS 36
#define LDBS 260
#define LDCS 260

// per-stage smem floats
#define STAGE_FLOATS (BM * LDAS + BK * LDBS)   // 2304 + 8320 = 10624
#define SMEM_BYTES (2 * STAGE_FLOATS * 4)      // 84992

// scratch (device globals; no allocations allowed)
__device__ float g_buf0[NN * DD];
__device__ float g_buf1[NN * DD];
__device__ float g_h[NN * DD];
__device__ float g_gout[NN * DD];
__device__ float g_deg[NN];

__device__ __forceinline__ void cp_async16(void* smem_ptr, const void* gmem_ptr)
{
    uint32_t s = (uint32_t)__cvta_generic_to_shared(smem_ptr);
    asm volatile("cp.async.cg.shared.global [%0], [%1], 16;\n" :: "r"(s), "l"(gmem_ptr));
}
#define CP_COMMIT() asm volatile("cp.async.commit_group;\n" ::)

// C = A[M,K] @ B[K,256]; if FUSE: Y = (resid + C) * 1/(rowsum(A)+1)
// Tile: BM=64 rows x BN=256 cols per CTA, grid (1, M/64). A read exactly once.
template <bool FUSE>
__global__ __launch_bounds__(256) void gemm_kernel(
    const float* __restrict__ A, int lda,
    const float* __restrict__ B, int ldb,
    int K,
    const float* __restrict__ resid,
    float* __restrict__ Y)
{
    extern __shared__ float pool[];
    // stage s: As = pool + s*STAGE_FLOATS, Bs = As + BM*LDAS
    __shared__ float invs[BM];

    const int tid = threadIdx.x;
    const int wid = tid >> 5;
    const int wm = wid >> 2;            // 0..1 : 32-row band
    const int wn = wid & 3;             // 0..3 : 64-col band
    const int m0 = blockIdx.y * BM;

    wmma::fragment<wmma::accumulator, 16, 16, 8, float> cf[2][4];
#pragma unroll
    for (int i = 0; i < 2; i++)
#pragma unroll
        for (int j = 0; j < 4; j++) wmma::fill_fragment(cf[i][j], 0.0f);

    float rs = 0.0f;                    // partial rowsum for row tid>>2
    const int nIter = K / BK;

    // ---- preload tile 0
    {
        float* As = pool;
        float* Bs = pool + BM * LDAS;
#pragma unroll
        for (int i = 0; i < 2; i++) {
            int e = tid + i * 256;       // 0..511
            int r = e >> 3, c4 = (e & 7) * 4;
            cp_async16(&As[r * LDAS + c4], &A[(size_t)(m0 + r) * lda + c4]);
        }
#pragma unroll
        for (int i = 0; i < 8; i++) {
            int e = tid + i * 256;       // 0..2047
            int r = e >> 6, c4 = (e & 63) * 4;
            cp_async16(&Bs[r * LDBS + c4], &B[(size_t)r * ldb + c4]);
        }
        CP_COMMIT();
    }

    for (int it = 0; it < nIter; ++it) {
        const int cur = it & 1;
        if (it + 1 < nIter) {
            const int nxt = (it + 1) & 1;
            const int k0 = (it + 1) * BK;
            float* As = pool + nxt * STAGE_FLOATS;
            float* Bs = As + BM * LDAS;
#pragma unroll
            for (int i = 0; i < 2; i++) {
                int e = tid + i * 256;
                int r = e >> 3, c4 = (e & 7) * 4;
                cp_async16(&As[r * LDAS + c4], &A[(size_t)(m0 + r) * lda + k0 + c4]);
            }
#pragma unroll
            for (int i = 0; i < 8; i++) {
                int e = tid + i * 256;
                int r = e >> 6, c4 = (e & 63) * 4;
                cp_async16(&Bs[r * LDBS + c4], &B[(size_t)(k0 + r) * ldb + c4]);
            }
            CP_COMMIT();
            asm volatile("cp.async.wait_group 1;\n" ::);
        } else {
            asm volatile("cp.async.wait_group 0;\n" ::);
        }
        __syncthreads();

        float* As = pool + cur * STAGE_FLOATS;
        float* Bs = As + BM * LDAS;

        if (FUSE) {
            // rowsum: thread group of 4 covers one row (8 floats each)
            const float* ap = &As[(tid >> 2) * LDAS + (tid & 3) * 8];
            float4 u = *(const float4*)ap;
            float4 v = *(const float4*)(ap + 4);
            rs += u.x + u.y + u.z + u.w + v.x + v.y + v.z + v.w;
        }

#pragma unroll
        for (int kk = 0; kk < BK; kk += 8) {
            wmma::fragment<wmma::matrix_a, 16, 16, 8, wmma::precision::tf32, wmma::row_major> af[2];
            wmma::fragment<wmma::matrix_b, 16, 16, 8, wmma::precision::tf32, wmma::row_major> bf[4];
#pragma unroll
            for (int i = 0; i < 2; i++) {
                wmma::load_matrix_sync(af[i], &As[(wm * 32 + i * 16) * LDAS + kk], LDAS);
#pragma unroll
                for (int t = 0; t < af[i].num_elements; t++)
                    af[i].x[t] = wmma::__float_to_tf32(af[i].x[t]);
            }
#pragma unroll
            for (int j = 0; j < 4; j++) {
                wmma::load_matrix_sync(bf[j], &Bs[kk * LDBS + wn * 64 + j * 16], LDBS);
#pragma unroll
                for (int t = 0; t < bf[j].num_elements; t++)
                    bf[j].x[t] = wmma::__float_to_tf32(bf[j].x[t]);
            }
#pragma unroll
            for (int i = 0; i < 2; i++)
#pragma unroll
                for (int j = 0; j < 4; j++)
                    wmma::mma_sync(cf[i][j], af[i], bf[j], cf[i][j]);
        }
        __syncthreads();
    }

    if (FUSE) {
        // reduce rowsum across the 4 threads covering each row
        float v = rs;
        v += __shfl_down_sync(0xffffffffu, v, 2, 4);
        v += __shfl_down_sync(0xffffffffu, v, 1, 4);
        if ((tid & 3) == 0) invs[tid >> 2] = 1.0f / (v + 1.0f);
        __syncthreads();
    }

    // stage C through shared (pool free after last sync)
    float* Cs = pool;
#pragma unroll
    for (int i = 0; i < 2; i++)
#pragma unroll
        for (int j = 0; j < 4; j++)
            wmma::store_matrix_sync(&Cs[(wm * 32 + i * 16) * LDCS + wn * 64 + j * 16],
                                    cf[i][j], LDCS, wmma::mem_row_major);
    __syncthreads();
#pragma unroll
    for (int i = 0; i < 16; i++) {
        int e = tid + i * 256;             // 0..4095
        int r = e >> 6, c4 = (e & 63) * 4;
        float4 c = *(float4*)&Cs[r * LDCS + c4];
        if (FUSE) {
            float4 x = *(const float4*)&resid[(size_t)(m0 + r) * DD + c4];
            float s = invs[r];
            c.x = (c.x + x.x) * s;
            c.y = (c.y + x.y) * s;
            c.z = (c.z + x.z) * s;
            c.w = (c.w + x.w) * s;
        }
        *(float4*)&Y[(size_t)(m0 + r) * DD + c4] = c;
    }
}

__global__ void deg_reset(float* deg)
{
    int i = blockIdx.x * blockDim.x + threadIdx.x;
    if (i < NN) deg[i] = 1.0f;   // self loop
}

__global__ void deg_count(const int* __restrict__ dst, float* deg)
{
    int e = blockIdx.x * blockDim.x + threadIdx.x;
    if (e < NE) atomicAdd(&deg[dst[e]], 1.0f);
}

// out[n,:] = b + (1/deg[n]) * h[n,:]   (self-loop term, norm = dinv^2)
__global__ void gcn_init(const float* __restrict__ h, const float* __restrict__ deg,
                         const float* __restrict__ b, float* __restrict__ out)
{
    int idx = blockIdx.x * blockDim.x + threadIdx.x;
    if (idx >= NN * (DD / 4)) return;
    int n = idx >> 6;
    int c4 = (idx & 63) * 4;
    float inv = 1.0f / deg[n];
    float4 hv = *(const float4*)&h[(size_t)n * DD + c4];
    float4 bv = *(const float4*)&b[c4];
    float4 o;
    o.x = bv.x + inv * hv.x;
    o.y = bv.y + inv * hv.y;
    o.z = bv.z + inv * hv.z;
    o.w = bv.w + inv * hv.w;
    *(float4*)&out[(size_t)n * DD + c4] = o;
}

__global__ void gcn_scatter(const int* __restrict__ src, const int* __restrict__ dst,
                            const float* __restrict__ h, const float* __restrict__ deg,
                            float* out)
{
    int idx = blockIdx.x * blockDim.x + threadIdx.x;
    if (idx >= NE * (DD / 4)) return;
    int e = idx >> 6;
    int c4 = (idx & 63) * 4;
    int s = src[e];
    int d = dst[e];
    float norm = rsqrtf(deg[s]) * rsqrtf(deg[d]);
    float4 hv = *(const float4*)&h[(size_t)s * DD + c4];
    float* o = &out[(size_t)d * DD + c4];
    asm volatile("red.global.add.v4.f32 [%0], {%1, %2, %3, %4};\n"
                 :: "l"(o), "f"(norm * hv.x), "f"(norm * hv.y),
                    "f"(norm * hv.z), "f"(norm * hv.w)
                 : "memory");
}

extern "C" void kernel_launch(void* const* d_in, const int* in_sizes, int n_in,
                              void* d_out, int out_size)
{
    const float* emb    = (const float*)d_in[0];
    const float* paths  = (const float*)d_in[1];
    const int*   sm_ei  = (const int*)d_in[2];
    const int*   up_ei  = (const int*)d_in[3];
    const float* W_same = (const float*)d_in[4];
    const float* b_same = (const float*)d_in[5];
    const float* W_top  = (const float*)d_in[6];
    const float* b_top  = (const float*)d_in[7];
    float* out = (float*)d_out;

    float *buf0, *buf1, *h, *gout, *deg;
    cudaGetSymbolAddress((void**)&buf0, g_buf0);
    cudaGetSymbolAddress((void**)&buf1, g_buf1);
    cudaGetSymbolAddress((void**)&h, g_h);
    cudaGetSymbolAddress((void**)&gout, g_gout);
    cudaGetSymbolAddress((void**)&deg, g_deg);

    static bool attr_done = false;
    if (!attr_done) {
        cudaFuncSetAttribute(gemm_kernel<true>,
                             cudaFuncAttributeMaxDynamicSharedMemorySize, SMEM_BYTES);
        cudaFuncSetAttribute(gemm_kernel<false>,
                             cudaFuncAttributeMaxDynamicSharedMemorySize, SMEM_BYTES);
        attr_done = true;
    }

    dim3 ggrid(1, NN / BM);   // (1, 128)
    dim3 gblk(256);

    // ---- bottom_to_up: level 0 and level 1
    gemm_kernel<true><<<ggrid, gblk, SMEM_BYTES>>>(paths, NN, emb, DD, NN, emb, buf0);
    gemm_kernel<true><<<ggrid, gblk, SMEM_BYTES>>>(paths + (size_t)NN * NN, NN, buf0, DD, NN, buf0, buf1);

    // ---- GCN 1 (same-level)
    gemm_kernel<false><<<ggrid, gblk, SMEM_BYTES>>>(buf1, DD, W_same, DD, DD, nullptr, h);
    deg_reset<<<(NN + 255) / 256, 256>>>(deg);
    deg_count<<<(NE + 255) / 256, 256>>>(sm_ei + NE, deg);
    gcn_init<<<(NN * (DD / 4) + 255) / 256, 256>>>(h, deg, b_same, gout);
    gcn_scatter<<<(NE * (DD / 4) + 255) / 256, 256>>>(sm_ei, sm_ei + NE, h, deg, gout);

    // ---- GCN 2 (top-to-bottom)
    gemm_kernel<false><<<ggrid, gblk, SMEM_BYTES>>>(gout, DD, W_top, DD, DD, nullptr, h);
    deg_reset<<<(NN + 255) / 256, 256>>>(deg);
    deg_count<<<(NE + 255) / 256, 256>>>(up_ei + NE, deg);
    gcn_init<<<(NN * (DD / 4) + 255) / 256, 256>>>(h, deg, b_top, out);
    gcn_scatter<<<(NE * (DD / 4) + 255) / 256, 256>>>(up_ei, up_ei + NE, h, deg, out);
}

// round 7
// speedup vs baseline: 1.1461x; 1.0264x over previous
#include <cuda_runtime.h>
#include <mma.h>
#include <cstdint>

using namespace nvcuda;

#define NN 8192
#define DD 256
#define NE 131072

#define BM 64
#define BN 256
#define BK 32
#define LDAS 36
#define LDBS 260
#define LDCS 260
#define STAGE_FLOATS (BM * LDAS + BK * LDBS)   // 10624
#define SMEM_BYTES (2 * STAGE_FLOATS * 4)      // 84992

// scratch (device globals; no allocations allowed)
__device__ float g_buf0[NN * DD];
__device__ float g_buf1[NN * DD];
__device__ float g_h[NN * DD];
__device__ float g_gout[NN * DD];
__device__ int   g_cnt[NN];
__device__ int   g_rowstart[NN + 1];
__device__ int   g_cursor[NN];
__device__ int   g_csr_src[NE];
__device__ float g_dinv[NN];

__device__ __forceinline__ void cp_async16(void* smem_ptr, const void* gmem_ptr)
{
    uint32_t s = (uint32_t)__cvta_generic_to_shared(smem_ptr);
    asm volatile("cp.async.cg.shared.global [%0], [%1], 16;\n" :: "r"(s), "l"(gmem_ptr));
}
#define CP_COMMIT() asm volatile("cp.async.commit_group;\n" ::)

// ---------------------------------------------------------------------------
// GEMM: C = A[M,K] @ B[K,256]; FUSE: Y = (resid + C) * 1/(rowsum(A)+1)
// BM=64 x BN=256 tile per CTA, grid (1, M/64). A read exactly once.
// CVT_B: RN-convert B fragments (accuracy) vs raw-bit truncation (speed).
// ---------------------------------------------------------------------------
template <bool FUSE, bool CVT_B>
__global__ __launch_bounds__(256) void gemm_kernel(
    const float* __restrict__ A, int lda,
    const float* __restrict__ B, int ldb,
    int K,
    const float* __restrict__ resid,
    float* __restrict__ Y)
{
    extern __shared__ float pool[];
    __shared__ float invs[BM];

    const int tid = threadIdx.x;
    const int wid = tid >> 5;
    const int wm = wid >> 2;            // 0..1 : 32-row band
    const int wn = wid & 3;             // 0..3 : 64-col band
    const int m0 = blockIdx.y * BM;

    wmma::fragment<wmma::accumulator, 16, 16, 8, float> cf[2][4];
#pragma unroll
    for (int i = 0; i < 2; i++)
#pragma unroll
        for (int j = 0; j < 4; j++) wmma::fill_fragment(cf[i][j], 0.0f);

    float rs = 0.0f;
    const int nIter = K / BK;

    {
        float* As = pool;
        float* Bs = pool + BM * LDAS;
#pragma unroll
        for (int i = 0; i < 2; i++) {
            int e = tid + i * 256;
            int r = e >> 3, c4 = (e & 7) * 4;
            cp_async16(&As[r * LDAS + c4], &A[(size_t)(m0 + r) * lda + c4]);
        }
#pragma unroll
        for (int i = 0; i < 8; i++) {
            int e = tid + i * 256;
            int r = e >> 6, c4 = (e & 63) * 4;
            cp_async16(&Bs[r * LDBS + c4], &B[(size_t)r * ldb + c4]);
        }
        CP_COMMIT();
    }

    for (int it = 0; it < nIter; ++it) {
        const int cur = it & 1;
        if (it + 1 < nIter) {
            const int nxt = (it + 1) & 1;
            const int k0 = (it + 1) * BK;
            float* As = pool + nxt * STAGE_FLOATS;
            float* Bs = As + BM * LDAS;
#pragma unroll
            for (int i = 0; i < 2; i++) {
                int e = tid + i * 256;
                int r = e >> 3, c4 = (e & 7) * 4;
                cp_async16(&As[r * LDAS + c4], &A[(size_t)(m0 + r) * lda + k0 + c4]);
            }
#pragma unroll
            for (int i = 0; i < 8; i++) {
                int e = tid + i * 256;
                int r = e >> 6, c4 = (e & 63) * 4;
                cp_async16(&Bs[r * LDBS + c4], &B[(size_t)(k0 + r) * ldb + c4]);
            }
            CP_COMMIT();
            asm volatile("cp.async.wait_group 1;\n" ::);
        } else {
            asm volatile("cp.async.wait_group 0;\n" ::);
        }
        __syncthreads();

        float* As = pool + cur * STAGE_FLOATS;
        float* Bs = As + BM * LDAS;

        if (FUSE) {
            const float* ap = &As[(tid >> 2) * LDAS + (tid & 3) * 8];
            float4 u = *(const float4*)ap;
            float4 v = *(const float4*)(ap + 4);
            rs += u.x + u.y + u.z + u.w + v.x + v.y + v.z + v.w;
        }

#pragma unroll
        for (int kk = 0; kk < BK; kk += 8) {
            wmma::fragment<wmma::matrix_a, 16, 16, 8, wmma::precision::tf32, wmma::row_major> af[2];
            wmma::fragment<wmma::matrix_b, 16, 16, 8, wmma::precision::tf32, wmma::row_major> bf[4];
#pragma unroll
            for (int i = 0; i < 2; i++) {
                wmma::load_matrix_sync(af[i], &As[(wm * 32 + i * 16) * LDAS + kk], LDAS);
#pragma unroll
                for (int t = 0; t < af[i].num_elements; t++)
                    af[i].x[t] = wmma::__float_to_tf32(af[i].x[t]);
            }
#pragma unroll
            for (int j = 0; j < 4; j++) {
                wmma::load_matrix_sync(bf[j], &Bs[kk * LDBS + wn * 64 + j * 16], LDBS);
                if (CVT_B) {
#pragma unroll
                    for (int t = 0; t < bf[j].num_elements; t++)
                        bf[j].x[t] = wmma::__float_to_tf32(bf[j].x[t]);
                }
            }
#pragma unroll
            for (int i = 0; i < 2; i++)
#pragma unroll
                for (int j = 0; j < 4; j++)
                    wmma::mma_sync(cf[i][j], af[i], bf[j], cf[i][j]);
        }
        __syncthreads();
    }

    if (FUSE) {
        float v = rs;
        v += __shfl_down_sync(0xffffffffu, v, 2, 4);
        v += __shfl_down_sync(0xffffffffu, v, 1, 4);
        if ((tid & 3) == 0) invs[tid >> 2] = 1.0f / (v + 1.0f);
        __syncthreads();
    }

    float* Cs = pool;
#pragma unroll
    for (int i = 0; i < 2; i++)
#pragma unroll
        for (int j = 0; j < 4; j++)
            wmma::store_matrix_sync(&Cs[(wm * 32 + i * 16) * LDCS + wn * 64 + j * 16],
                                    cf[i][j], LDCS, wmma::mem_row_major);
    __syncthreads();
#pragma unroll
    for (int i = 0; i < 16; i++) {
        int e = tid + i * 256;
        int r = e >> 6, c4 = (e & 63) * 4;
        float4 c = *(float4*)&Cs[r * LDCS + c4];
        if (FUSE) {
            float4 x = *(const float4*)&resid[(size_t)(m0 + r) * DD + c4];
            float s = invs[r];
            c.x = (c.x + x.x) * s;
            c.y = (c.y + x.y) * s;
            c.z = (c.z + x.z) * s;
            c.w = (c.w + x.w) * s;
        }
        *(float4*)&Y[(size_t)(m0 + r) * DD + c4] = c;
    }
}

// ---------------------------------------------------------------------------
// CSR build + gather GCN
// ---------------------------------------------------------------------------
__global__ void zero_cnt_kernel()
{
    int i = blockIdx.x * blockDim.x + threadIdx.x;
    if (i < NN) g_cnt[i] = 0;
}

__global__ void hist_kernel(const int* __restrict__ dst)
{
    int e = blockIdx.x * blockDim.x + threadIdx.x;
    if (e < NE) atomicAdd(&g_cnt[dst[e]], 1);
}

// one block, 1024 threads: exclusive scan of g_cnt -> rowstart/cursor, dinv
__global__ __launch_bounds__(1024) void scan_kernel()
{
    __shared__ int sh[1024];
    int t = threadIdx.x;
    int base = t * 8;
    int v[8];
    int s = 0;
#pragma unroll
    for (int i = 0; i < 8; i++) { v[i] = g_cnt[base + i]; s += v[i]; }
    sh[t] = s;
    __syncthreads();
    for (int off = 1; off < 1024; off <<= 1) {
        int x = (t >= off) ? sh[t - off] : 0;
        __syncthreads();
        sh[t] += x;
        __syncthreads();
    }
    int ex = sh[t] - s;
#pragma unroll
    for (int i = 0; i < 8; i++) {
        g_rowstart[base + i] = ex;
        g_cursor[base + i] = ex;
        g_dinv[base + i] = rsqrtf((float)v[i] + 1.0f);
        ex += v[i];
    }
    if (t == 1023) g_rowstart[NN] = ex;
}

__global__ void fill_kernel(const int* __restrict__ src, const int* __restrict__ dst)
{
    int e = blockIdx.x * blockDim.x + threadIdx.x;
    if (e >= NE) return;
    int p = atomicAdd(&g_cursor[dst[e]], 1);
    g_csr_src[p] = src[e];
}

// warp-per-node gather: out[n] = b + dinv[n]^2*h[n] + sum_e dinv[s]*dinv[n]*h[s]
__global__ __launch_bounds__(256) void gather_kernel(
    const float* __restrict__ h, const float* __restrict__ b, float* __restrict__ out)
{
    int wid = threadIdx.x >> 5;
    int lid = threadIdx.x & 31;
    int n = blockIdx.x * 8 + wid;
    if (n >= NN) return;
    int c0 = lid * 8;

    float dn = g_dinv[n];
    float4 b0 = *(const float4*)&b[c0];
    float4 b1 = *(const float4*)&b[c0 + 4];
    float4 h0 = *(const float4*)&h[(size_t)n * DD + c0];
    float4 h1 = *(const float4*)&h[(size_t)n * DD + c0 + 4];
    float sl = dn * dn;
    float4 a0, a1;
    a0.x = b0.x + sl * h0.x; a0.y = b0.y + sl * h0.y;
    a0.z = b0.z + sl * h0.z; a0.w = b0.w + sl * h0.w;
    a1.x = b1.x + sl * h1.x; a1.y = b1.y + sl * h1.y;
    a1.z = b1.z + sl * h1.z; a1.w = b1.w + sl * h1.w;

    int js = g_rowstart[n];
    int je = g_rowstart[n + 1];
    int j = js;
    for (; j + 1 < je; j += 2) {
        int s0 = g_csr_src[j];
        int s1 = g_csr_src[j + 1];
        float w0 = g_dinv[s0] * dn;
        float w1 = g_dinv[s1] * dn;
        float4 p0 = *(const float4*)&h[(size_t)s0 * DD + c0];
        float4 p1 = *(const float4*)&h[(size_t)s0 * DD + c0 + 4];
        float4 q0 = *(const float4*)&h[(size_t)s1 * DD + c0];
        float4 q1 = *(const float4*)&h[(size_t)s1 * DD + c0 + 4];
        a0.x += w0 * p0.x + w1 * q0.x; a0.y += w0 * p0.y + w1 * q0.y;
        a0.z += w0 * p0.z + w1 * q0.z; a0.w += w0 * p0.w + w1 * q0.w;
        a1.x += w0 * p1.x + w1 * q1.x; a1.y += w0 * p1.y + w1 * q1.y;
        a1.z += w0 * p1.z + w1 * q1.z; a1.w += w0 * p1.w + w1 * q1.w;
    }
    if (j < je) {
        int s0 = g_csr_src[j];
        float w0 = g_dinv[s0] * dn;
        float4 p0 = *(const float4*)&h[(size_t)s0 * DD + c0];
        float4 p1 = *(const float4*)&h[(size_t)s0 * DD + c0 + 4];
        a0.x += w0 * p0.x; a0.y += w0 * p0.y; a0.z += w0 * p0.z; a0.w += w0 * p0.w;
        a1.x += w0 * p1.x; a1.y += w0 * p1.y; a1.z += w0 * p1.z; a1.w += w0 * p1.w;
    }
    *(float4*)&out[(size_t)n * DD + c0] = a0;
    *(float4*)&out[(size_t)n * DD + c0 + 4] = a1;
}

extern "C" void kernel_launch(void* const* d_in, const int* in_sizes, int n_in,
                              void* d_out, int out_size)
{
    const float* emb    = (const float*)d_in[0];
    const float* paths  = (const float*)d_in[1];
    const int*   sm_ei  = (const int*)d_in[2];
    const int*   up_ei  = (const int*)d_in[3];
    const float* W_same = (const float*)d_in[4];
    const float* b_same = (const float*)d_in[5];
    const float* W_top  = (const float*)d_in[6];
    const float* b_top  = (const float*)d_in[7];
    float* out = (float*)d_out;

    float *buf0, *buf1, *h, *gout;
    cudaGetSymbolAddress((void**)&buf0, g_buf0);
    cudaGetSymbolAddress((void**)&buf1, g_buf1);
    cudaGetSymbolAddress((void**)&h, g_h);
    cudaGetSymbolAddress((void**)&gout, g_gout);

    cudaFuncSetAttribute(gemm_kernel<true, false>,
                         cudaFuncAttributeMaxDynamicSharedMemorySize, SMEM_BYTES);
    cudaFuncSetAttribute(gemm_kernel<false, true>,
                         cudaFuncAttributeMaxDynamicSharedMemorySize, SMEM_BYTES);

    dim3 ggrid(1, NN / BM);   // (1, 128)

    // ---- bottom_to_up: level 0 and level 1 (B truncated to tf32 in HW)
    gemm_kernel<true, false><<<ggrid, 256, SMEM_BYTES>>>(paths, NN, emb, DD, NN, emb, buf0);
    gemm_kernel<true, false><<<ggrid, 256, SMEM_BYTES>>>(paths + (size_t)NN * NN, NN, buf0, DD, NN, buf0, buf1);

    // ---- GCN 1 (same-level)
    gemm_kernel<false, true><<<ggrid, 256, SMEM_BYTES>>>(buf1, DD, W_same, DD, DD, nullptr, h);
    zero_cnt_kernel<<<NN / 256, 256>>>();
    hist_kernel<<<NE / 256, 256>>>(sm_ei + NE);
    scan_kernel<<<1, 1024>>>();
    fill_kernel<<<NE / 256, 256>>>(sm_ei, sm_ei + NE);
    gather_kernel<<<NN / 8, 256>>>(h, b_same, gout);

    // ---- GCN 2 (top-to-bottom)
    gemm_kernel<false, true><<<ggrid, 256, SMEM_BYTES>>>(gout, DD, W_top, DD, DD, nullptr, h);
    zero_cnt_kernel<<<NN / 256, 256>>>();
    hist_kernel<<<NE / 256, 256>>>(up_ei + NE);
    scan_kernel<<<1, 1024>>>();
    fill_kernel<<<NE / 256, 256>>>(up_ei, up_ei + NE);
    gather_kernel<<<NN / 8, 256>>>(h, b_top, out);
}